// round 1
// baseline (speedup 1.0000x reference)
#include <cuda_runtime.h>
#include <math.h>
#include <stdint.h>

#define HW 128
#define NPIX 16384
#define BATCH 2
#define KJ 128
#define NPAIR 8128
#define NROWS (BATCH * NPAIR)   // 16256
#define DLOI 128
#define DFC 1024

// ---------------- scratch (device globals; no allocations allowed) ----------
__device__ float g_xf[BATCH * NPIX * DLOI];   // (b, pix, d) transposed layout
__device__ float g_xy[BATCH][KJ][2];          // (y, x) per junction
__device__ float g_xv[(size_t)NROWS * DFC];   // pooled features, row-major
__device__ float g_h1[(size_t)NROWS * DFC];
__device__ float g_h2[(size_t)NROWS * DFC];

// ---------------- pair index helpers (triu_indices(K=128, k=1)) -------------
__device__ __forceinline__ int pair_off(int u) { return u * (255 - u) / 2; }

__device__ __forceinline__ void pair_uv(int p, int& u, int& v) {
    int uu = (int)((255.0 - sqrt(255.0 * 255.0 - 8.0 * (double)p)) * 0.5);
    if (uu < 0) uu = 0;
    if (uu > 126) uu = 126;
    while (uu < 126 && pair_off(uu + 1) <= p) uu++;
    while (uu > 0 && pair_off(uu) > p) uu--;
    u = uu;
    v = uu + 1 + (p - pair_off(uu));
}

// ---------------- K1: jmap + NMS + exact top-128 + junction coords ----------
// One block per batch, 512 threads. Shared: smap(64KB) + nmsv(64KB) + reduce.
__global__ void k_topk(const float* __restrict__ inputs) {
    extern __shared__ float sh[];
    float* smap = sh;                    // 16384
    float* nmsv = smap + NPIX;           // 16384
    float* bv   = nmsv + NPIX;           // 512
    int*   bi   = (int*)(bv + 512);      // 512
    float* wv   = (float*)(bi + 512);    // 16
    int*   wi   = (int*)(wv + 16);       // 16
    int*   topidx = wi + 16;             // 128

    const int b = blockIdx.x;
    const int t = threadIdx.x;
    const float* in0 = inputs + (size_t)b * 5 * NPIX;
    const float* in1 = in0 + NPIX;

    // jmap = softmax over {ch0, ch1} taking ch1 (max-subtracted like XLA)
    for (int i = t; i < NPIX; i += 512) {
        float x0 = in0[i], x1 = in1[i];
        float m = fmaxf(x0, x1);
        float e0 = expf(x0 - m), e1 = expf(x1 - m);
        smap[i] = e1 / (e0 + e1);
    }
    __syncthreads();

    // NMS over 3x3 SAME window; local best per thread-chunk of 32
    float bval = -1.0f;
    int bidx = t * 32;
    for (int j = 0; j < 32; j++) {
        int idx = t * 32 + j;
        int y = idx >> 7, x = idx & 127;
        float v = smap[idx];
        float m = v;
        #pragma unroll
        for (int dy = -1; dy <= 1; dy++) {
            int yy = y + dy;
            if (yy < 0 || yy >= HW) continue;
            #pragma unroll
            for (int dx = -1; dx <= 1; dx++) {
                int xx = x + dx;
                if (xx < 0 || xx >= HW) continue;
                m = fmaxf(m, smap[yy * HW + xx]);
            }
        }
        float nv = (v == m) ? v : 0.0f;
        nmsv[idx] = nv;
        if (nv > bval) { bval = nv; bidx = idx; }   // strict > => lowest idx on tie
    }
    bv[t] = bval; bi[t] = bidx;
    __syncthreads();

    // 128 rounds of (value desc, index asc) arg-max selection
    for (int r = 0; r < KJ; r++) {
        float v = bv[t];
        int ix = bi[t];
        #pragma unroll
        for (int off = 16; off; off >>= 1) {
            float v2 = __shfl_down_sync(0xffffffffu, v, off);
            int   i2 = __shfl_down_sync(0xffffffffu, ix, off);
            if (v2 > v || (v2 == v && i2 < ix)) { v = v2; ix = i2; }
        }
        if ((t & 31) == 0) { wv[t >> 5] = v; wi[t >> 5] = ix; }
        __syncthreads();
        if (t < 32) {
            float v3 = (t < 16) ? wv[t] : -2.0f;
            int   i3 = (t < 16) ? wi[t] : 0x7fffffff;
            #pragma unroll
            for (int off = 8; off; off >>= 1) {
                float v2 = __shfl_down_sync(0xffffffffu, v3, off);
                int   i2 = __shfl_down_sync(0xffffffffu, i3, off);
                if (v2 > v3 || (v2 == v3 && i2 < i3)) { v3 = v2; i3 = i2; }
            }
            if (t == 0) topidx[r] = i3;
        }
        __syncthreads();
        int win = topidx[r];
        if (t == (win >> 5)) {   // owner invalidates + rescans its 32 keys
            nmsv[win] = -1.0f;
            float nb = -1.0f;
            int nbi = t * 32;
            for (int j = 0; j < 32; j++) {
                float nv = nmsv[t * 32 + j];
                if (nv > nb) { nb = nv; nbi = t * 32 + j; }
            }
            bv[t] = nb; bi[t] = nbi;
        }
        __syncthreads();
    }

    if (t < KJ) {
        int idx = topidx[t];
        const float* in3 = in0 + 3 * NPIX;
        const float* in4 = in0 + 4 * NPIX;
        // y = row + (sigmoid - 0.5) + 0.5 = row + sigmoid
        float sy = 1.0f / (1.0f + expf(-in3[idx]));
        float sx = 1.0f / (1.0f + expf(-in4[idx]));
        g_xy[b][t][0] = (float)(idx >> 7) + sy;
        g_xy[b][t][1] = (float)(idx & 127) + sx;
    }
}

// ---------------- K2: xf[b,pix,d] = sum_c features[b,c,pix]*fc1_w[d,c] + b --
// Block: 32 pixels x 128 d, 256 threads (thread = 4 px x 4 d).
__global__ __launch_bounds__(256) void k_xf(const float* __restrict__ features,
                                            const float* __restrict__ fc1_w,
                                            const float* __restrict__ fc1_b) {
    __shared__ float As[32][40];    // [c][px], padded for 16B-aligned rows
    __shared__ float Ws[32][128];   // [c][d]
    const int b = blockIdx.y;
    const int pixbase = blockIdx.x * 32;
    const int t = threadIdx.x;
    const int pxq = t & 7;    // pixel quad
    const int dq  = t >> 3;   // d quad
    float acc[4][4] = {};

    const float* F = features + (size_t)b * 256 * NPIX + pixbase;

    for (int c0 = 0; c0 < 256; c0 += 32) {
        {
            int c = t >> 3, px4 = (t & 7) * 4;
            float4 a4 = *(const float4*)(F + (size_t)(c0 + c) * NPIX + px4);
            As[c][px4 + 0] = a4.x; As[c][px4 + 1] = a4.y;
            As[c][px4 + 2] = a4.z; As[c][px4 + 3] = a4.w;
        }
        #pragma unroll
        for (int kk = 0; kk < 4; kk++) {
            int e = t + kk * 256;
            int d = e >> 3, c4 = (e & 7) * 4;
            float4 w4 = *(const float4*)(fc1_w + d * 256 + c0 + c4);
            Ws[c4 + 0][d] = w4.x; Ws[c4 + 1][d] = w4.y;
            Ws[c4 + 2][d] = w4.z; Ws[c4 + 3][d] = w4.w;
        }
        __syncthreads();
        #pragma unroll
        for (int c = 0; c < 32; c++) {
            float4 a4 = *(const float4*)&As[c][pxq * 4];
            float4 w4 = *(const float4*)&Ws[c][dq * 4];
            float av[4] = {a4.x, a4.y, a4.z, a4.w};
            float wr[4] = {w4.x, w4.y, w4.z, w4.w};
            #pragma unroll
            for (int i = 0; i < 4; i++)
                #pragma unroll
                for (int j = 0; j < 4; j++)
                    acc[i][j] += av[i] * wr[j];
        }
        __syncthreads();
    }

    float4 bb = *(const float4*)(fc1_b + dq * 4);
    #pragma unroll
    for (int i = 0; i < 4; i++) {
        int pix = pixbase + pxq * 4 + i;
        float4 o;
        o.x = acc[i][0] + bb.x; o.y = acc[i][1] + bb.y;
        o.z = acc[i][2] + bb.z; o.w = acc[i][3] + bb.w;
        *(float4*)(g_xf + ((size_t)b * NPIX + pix) * DLOI + dq * 4) = o;
    }
}

// ---------------- K3: LOI pool --> g_xv[row, d*8+g] -------------------------
__global__ __launch_bounds__(128) void k_pool() {
    const int gp = blockIdx.x;           // 0..16255
    const int b = gp / NPAIR;
    const int p = gp - b * NPAIR;
    int u, v;
    pair_uv(p, u, v);
    const int d = threadIdx.x;

    const float yu = g_xy[b][u][0], xu = g_xy[b][u][1];
    const float yv = g_xy[b][v][0], xv = g_xy[b][v][1];
    const float* xf = g_xf + (size_t)b * NPIX * DLOI + d;

    __shared__ float stage[1024];
    float gmax = -INFINITY;
    #pragma unroll
    for (int j = 0; j < 32; j++) {
        float lam = (float)j / 31.0f;
        float oml = 1.0f - lam;
        float fy = yu * lam + yv * oml - 0.5f;
        float fx = xu * lam + xv * oml - 0.5f;
        float y0f = fminf(fmaxf(floorf(fy), 0.0f), 127.0f);
        float x0f = fminf(fmaxf(floorf(fx), 0.0f), 127.0f);
        float y1f = fminf(y0f + 1.0f, 127.0f);
        float x1f = fminf(x0f + 1.0f, 127.0f);
        int y0 = (int)y0f, x0 = (int)x0f, y1 = (int)y1f, x1 = (int)x1f;
        float wy0 = fy - y0f, wy1 = y1f - fy;
        float wx0 = fx - x0f, wx1 = x1f - fx;
        float v00 = xf[(y0 * HW + x0) * DLOI];
        float v10 = xf[(y1 * HW + x0) * DLOI];
        float v01 = xf[(y0 * HW + x1) * DLOI];
        float v11 = xf[(y1 * HW + x1) * DLOI];
        float val = v00 * wy1 * wx1 + v10 * wy0 * wx1
                  + v01 * wy1 * wx0 + v11 * wy0 * wx0;
        gmax = fmaxf(gmax, val);
        if ((j & 3) == 3) { stage[d * 8 + (j >> 2)] = gmax; gmax = -INFINITY; }
    }
    __syncthreads();
    float* out = g_xv + (size_t)gp * 1024;
    #pragma unroll
    for (int i = 0; i < 8; i++) out[d + i * 128] = stage[d + i * 128];
}

// ---------------- K4/K5: fp32 SGEMM + bias (+relu). C = A(MxK) * B(KxN) -----
// BM=BN=128, BK=8, 256 threads, 8x8 per thread. M%128==0, N%128==0, K%8==0.
__global__ __launch_bounds__(256) void sgemm_bias_relu(
        const float* __restrict__ A, const float* __restrict__ B,
        const float* __restrict__ bias, float* __restrict__ C,
        int M, int N, int K, int doRelu) {
    __shared__ float As[8][128];
    __shared__ float Bs[8][128];
    const int bm = blockIdx.y * 128;
    const int bn = blockIdx.x * 128;
    const int t = threadIdx.x;
    const int tr = t / 16, tc = t % 16;

    float acc[8][8] = {};
    const int aRow = t >> 1, aCol = (t & 1) * 4;
    const int bRow = t >> 5, bCol = (t & 31) * 4;
    const float* Ap = A + (size_t)bm * K;
    const float* Bp = B + bn;

    for (int k0 = 0; k0 < K; k0 += 8) {
        float4 a4 = *(const float4*)(Ap + (size_t)aRow * K + k0 + aCol);
        As[aCol + 0][aRow] = a4.x; As[aCol + 1][aRow] = a4.y;
        As[aCol + 2][aRow] = a4.z; As[aCol + 3][aRow] = a4.w;
        float4 b4 = *(const float4*)(Bp + (size_t)(k0 + bRow) * N + bCol);
        *(float4*)&Bs[bRow][bCol] = b4;
        __syncthreads();
        #pragma unroll
        for (int k = 0; k < 8; k++) {
            float ra[8], rb[8];
            *(float4*)&ra[0] = *(float4*)&As[k][tr * 8];
            *(float4*)&ra[4] = *(float4*)&As[k][tr * 8 + 4];
            *(float4*)&rb[0] = *(float4*)&Bs[k][tc * 8];
            *(float4*)&rb[4] = *(float4*)&Bs[k][tc * 8 + 4];
            #pragma unroll
            for (int i = 0; i < 8; i++)
                #pragma unroll
                for (int j = 0; j < 8; j++)
                    acc[i][j] += ra[i] * rb[j];
        }
        __syncthreads();
    }

    #pragma unroll
    for (int i = 0; i < 8; i++) {
        int row = bm + tr * 8 + i;
        #pragma unroll
        for (int j4 = 0; j4 < 2; j4++) {
            float4 o;
            float* a = &acc[i][j4 * 4];
            const float* bp = bias + bn + tc * 8 + j4 * 4;
            o.x = a[0] + bp[0]; o.y = a[1] + bp[1];
            o.z = a[2] + bp[2]; o.w = a[3] + bp[3];
            if (doRelu) {
                o.x = fmaxf(o.x, 0.f); o.y = fmaxf(o.y, 0.f);
                o.z = fmaxf(o.z, 0.f); o.w = fmaxf(o.w, 0.f);
            }
            *(float4*)(C + (size_t)row * N + bn + tc * 8 + j4 * 4) = o;
        }
    }
}

// ---------------- K6: scores = h2 @ w3 + b3 (one warp per row) --------------
__global__ __launch_bounds__(256) void k_final(const float* __restrict__ w3,
                                               const float* __restrict__ b3,
                                               float* __restrict__ outScores) {
    const int row = blockIdx.x * 8 + (threadIdx.x >> 5);
    const int lane = threadIdx.x & 31;
    const float* h = g_h2 + (size_t)row * 1024;
    float s = 0.0f;
    #pragma unroll 8
    for (int i = lane; i < 1024; i += 32) s += h[i] * w3[i];
    #pragma unroll
    for (int off = 16; off; off >>= 1) s += __shfl_down_sync(0xffffffffu, s, off);
    if (lane == 0) outScores[row] = s + b3[0];
}

// ---------------- K7: labels (zeros) + lines --------------------------------
__global__ void k_out(float* __restrict__ out) {
    const int gp = blockIdx.x * 256 + threadIdx.x;
    if (gp >= NROWS) return;
    out[NROWS + gp] = 0.0f;                 // labels
    const int b = gp / NPAIR;
    const int p = gp - b * NPAIR;
    int u, v;
    pair_uv(p, u, v);
    float* L = out + 2 * NROWS + (size_t)gp * 4;
    L[0] = g_xy[b][u][0];
    L[1] = g_xy[b][u][1];
    L[2] = g_xy[b][v][0];
    L[3] = g_xy[b][v][1];
}

// ---------------- launch -----------------------------------------------------
extern "C" void kernel_launch(void* const* d_in, const int* in_sizes, int n_in,
                              void* d_out, int out_size) {
    const float* inputs   = (const float*)d_in[0];
    const float* features = (const float*)d_in[1];
    const float* fc1_w    = (const float*)d_in[2];
    const float* fc1_b    = (const float*)d_in[3];
    const float* w1       = (const float*)d_in[4];
    const float* b1       = (const float*)d_in[5];
    const float* w2       = (const float*)d_in[6];
    const float* b2       = (const float*)d_in[7];
    const float* w3       = (const float*)d_in[8];
    const float* b3       = (const float*)d_in[9];
    float* out = (float*)d_out;

    void *pxv, *ph1, *ph2;
    cudaGetSymbolAddress(&pxv, g_xv);
    cudaGetSymbolAddress(&ph1, g_h1);
    cudaGetSymbolAddress(&ph2, g_h2);

    const size_t topk_smem = (size_t)(NPIX * 2 + 512) * 4 + 512 * 4 + 64 + 64 + 512;
    cudaFuncSetAttribute(k_topk, cudaFuncAttributeMaxDynamicSharedMemorySize,
                         (int)topk_smem);

    k_topk<<<BATCH, 512, topk_smem>>>(inputs);
    k_xf<<<dim3(NPIX / 32, BATCH), 256>>>(features, fc1_w, fc1_b);
    k_pool<<<NROWS, 128>>>();

    dim3 gmm(DFC / 128, NROWS / 128);  // (8, 127)
    sgemm_bias_relu<<<gmm, 256>>>((const float*)pxv, w1, b1, (float*)ph1,
                                  NROWS, DFC, DFC, 1);
    sgemm_bias_relu<<<gmm, 256>>>((const float*)ph1, w2, b2, (float*)ph2,
                                  NROWS, DFC, DFC, 1);

    k_final<<<NROWS / 8, 256>>>(w3, b3, out);
    k_out<<<(NROWS + 255) / 256, 256>>>(out);
}

// round 3
// speedup vs baseline: 1.7642x; 1.7642x over previous
#include <cuda_runtime.h>
#include <cuda_bf16.h>
#include <math.h>
#include <stdint.h>

#define HW 128
#define NPIX 16384
#define BATCH 2
#define KJ 128
#define NPAIR 8128
#define NROWS (BATCH * NPAIR)   // 16256
#define DLOI 128
#define DFC 1024

// ---------------- scratch (device globals; no allocations allowed) ----------
__device__ float g_xf[BATCH * NPIX * DLOI];   // (b, pix, d)
__device__ float g_xy[BATCH][KJ][2];          // (y, x) per junction
__device__ __align__(16) __nv_bfloat16 g_xv_hi[(size_t)NROWS * DFC];
__device__ __align__(16) __nv_bfloat16 g_xv_lo[(size_t)NROWS * DFC];
__device__ __align__(16) __nv_bfloat16 g_h1_hi[(size_t)NROWS * DFC];
__device__ __align__(16) __nv_bfloat16 g_h1_lo[(size_t)NROWS * DFC];
__device__ __align__(16) __nv_bfloat16 g_w1t_hi[DFC * DFC];
__device__ __align__(16) __nv_bfloat16 g_w1t_lo[DFC * DFC];
__device__ __align__(16) __nv_bfloat16 g_w2t_hi[DFC * DFC];
__device__ __align__(16) __nv_bfloat16 g_w2t_lo[DFC * DFC];
__device__ float g_part[(size_t)NROWS * 8];

// ---------------- helpers ----------------------------------------------------
__device__ __forceinline__ uint32_t smem_u32(const void* p) {
    uint32_t a;
    asm("{ .reg .u64 t; cvta.to.shared.u64 t, %1; cvt.u32.u64 %0, t; }"
        : "=r"(a) : "l"(p));
    return a;
}
__device__ __forceinline__ void cp16(uint32_t s, const void* g) {
    asm volatile("cp.async.cg.shared.global [%0], [%1], 16;"
                 :: "r"(s), "l"(g) : "memory");
}
#define CP_COMMIT() asm volatile("cp.async.commit_group;" ::: "memory")
#define CP_WAIT(n)  asm volatile("cp.async.wait_group %0;" :: "n"(n) : "memory")

__device__ __forceinline__ void ldm_x4(uint32_t* r, uint32_t addr) {
    asm volatile("ldmatrix.sync.aligned.m8n8.x4.shared.b16 {%0,%1,%2,%3}, [%4];"
                 : "=r"(r[0]), "=r"(r[1]), "=r"(r[2]), "=r"(r[3]) : "r"(addr));
}
__device__ __forceinline__ void mma16816(float* c, const uint32_t* a,
                                         const uint32_t* b) {
    asm volatile(
        "mma.sync.aligned.m16n8k16.row.col.f32.bf16.bf16.f32 "
        "{%0,%1,%2,%3}, {%4,%5,%6,%7}, {%8,%9}, {%0,%1,%2,%3};"
        : "+f"(c[0]), "+f"(c[1]), "+f"(c[2]), "+f"(c[3])
        : "r"(a[0]), "r"(a[1]), "r"(a[2]), "r"(a[3]), "r"(b[0]), "r"(b[1]));
}

// ---------------- pair index helpers (triu_indices(K=128, k=1)) -------------
__device__ __forceinline__ int pair_off(int u) { return u * (255 - u) / 2; }
__device__ __forceinline__ void pair_uv(int p, int& u, int& v) {
    int uu = (int)((255.0 - sqrt(255.0 * 255.0 - 8.0 * (double)p)) * 0.5);
    if (uu < 0) uu = 0;
    if (uu > 126) uu = 126;
    while (uu < 126 && pair_off(uu + 1) <= p) uu++;
    while (uu > 0 && pair_off(uu) > p) uu--;
    u = uu;
    v = uu + 1 + (p - pair_off(uu));
}

// ---------------- K1: jmap + NMS + exact top-128 + junction coords ----------
__global__ void k_topk(const float* __restrict__ inputs) {
    extern __shared__ float sh[];
    float* smap = sh;
    float* nmsv = smap + NPIX;
    float* bv   = nmsv + NPIX;
    int*   bi   = (int*)(bv + 512);
    float* wv   = (float*)(bi + 512);
    int*   wi   = (int*)(wv + 16);
    int*   topidx = wi + 16;

    const int b = blockIdx.x;
    const int t = threadIdx.x;
    const float* in0 = inputs + (size_t)b * 5 * NPIX;
    const float* in1 = in0 + NPIX;

    for (int i = t; i < NPIX; i += 512) {
        float x0 = in0[i], x1 = in1[i];
        float m = fmaxf(x0, x1);
        float e0 = expf(x0 - m), e1 = expf(x1 - m);
        smap[i] = e1 / (e0 + e1);
    }
    __syncthreads();

    float bval = -1.0f;
    int bidx = t * 32;
    for (int j = 0; j < 32; j++) {
        int idx = t * 32 + j;
        int y = idx >> 7, x = idx & 127;
        float v = smap[idx];
        float m = v;
        #pragma unroll
        for (int dy = -1; dy <= 1; dy++) {
            int yy = y + dy;
            if (yy < 0 || yy >= HW) continue;
            #pragma unroll
            for (int dx = -1; dx <= 1; dx++) {
                int xx = x + dx;
                if (xx < 0 || xx >= HW) continue;
                m = fmaxf(m, smap[yy * HW + xx]);
            }
        }
        float nv = (v == m) ? v : 0.0f;
        nmsv[idx] = nv;
        if (nv > bval) { bval = nv; bidx = idx; }
    }
    bv[t] = bval; bi[t] = bidx;
    __syncthreads();

    for (int r = 0; r < KJ; r++) {
        float v = bv[t];
        int ix = bi[t];
        #pragma unroll
        for (int off = 16; off; off >>= 1) {
            float v2 = __shfl_down_sync(0xffffffffu, v, off);
            int   i2 = __shfl_down_sync(0xffffffffu, ix, off);
            if (v2 > v || (v2 == v && i2 < ix)) { v = v2; ix = i2; }
        }
        if ((t & 31) == 0) { wv[t >> 5] = v; wi[t >> 5] = ix; }
        __syncthreads();
        if (t < 32) {
            float v3 = (t < 16) ? wv[t] : -2.0f;
            int   i3 = (t < 16) ? wi[t] : 0x7fffffff;
            #pragma unroll
            for (int off = 8; off; off >>= 1) {
                float v2 = __shfl_down_sync(0xffffffffu, v3, off);
                int   i2 = __shfl_down_sync(0xffffffffu, i3, off);
                if (v2 > v3 || (v2 == v3 && i2 < i3)) { v3 = v2; i3 = i2; }
            }
            if (t == 0) topidx[r] = i3;
        }
        __syncthreads();
        int win = topidx[r];
        if (t == (win >> 5)) {
            nmsv[win] = -1.0f;
            float nb = -1.0f;
            int nbi = t * 32;
            for (int j = 0; j < 32; j++) {
                float nv = nmsv[t * 32 + j];
                if (nv > nb) { nb = nv; nbi = t * 32 + j; }
            }
            bv[t] = nb; bi[t] = nbi;
        }
        __syncthreads();
    }

    if (t < KJ) {
        int idx = topidx[t];
        const float* in3 = in0 + 3 * NPIX;
        const float* in4 = in0 + 4 * NPIX;
        float sy = 1.0f / (1.0f + expf(-in3[idx]));
        float sx = 1.0f / (1.0f + expf(-in4[idx]));
        g_xy[b][t][0] = (float)(idx >> 7) + sy;
        g_xy[b][t][1] = (float)(idx & 127) + sx;
    }
}

// ---------------- K2: xf[b,pix,d] = sum_c features[b,c,pix]*fc1_w[d,c]+b ----
__global__ __launch_bounds__(256) void k_xf(const float* __restrict__ features,
                                            const float* __restrict__ fc1_w,
                                            const float* __restrict__ fc1_b) {
    __shared__ float As[32][40];
    __shared__ float Ws[32][128];
    const int b = blockIdx.y;
    const int pixbase = blockIdx.x * 32;
    const int t = threadIdx.x;
    const int pxq = t & 7;
    const int dq  = t >> 3;
    float acc[4][4] = {};

    const float* F = features + (size_t)b * 256 * NPIX + pixbase;

    for (int c0 = 0; c0 < 256; c0 += 32) {
        {
            int c = t >> 3, px4 = (t & 7) * 4;
            float4 a4 = *(const float4*)(F + (size_t)(c0 + c) * NPIX + px4);
            As[c][px4 + 0] = a4.x; As[c][px4 + 1] = a4.y;
            As[c][px4 + 2] = a4.z; As[c][px4 + 3] = a4.w;
        }
        #pragma unroll
        for (int kk = 0; kk < 4; kk++) {
            int e = t + kk * 256;
            int d = e >> 3, c4 = (e & 7) * 4;
            float4 w4 = *(const float4*)(fc1_w + d * 256 + c0 + c4);
            Ws[c4 + 0][d] = w4.x; Ws[c4 + 1][d] = w4.y;
            Ws[c4 + 2][d] = w4.z; Ws[c4 + 3][d] = w4.w;
        }
        __syncthreads();
        #pragma unroll
        for (int c = 0; c < 32; c++) {
            float4 a4 = *(const float4*)&As[c][pxq * 4];
            float4 w4 = *(const float4*)&Ws[c][dq * 4];
            float av[4] = {a4.x, a4.y, a4.z, a4.w};
            float wr[4] = {w4.x, w4.y, w4.z, w4.w};
            #pragma unroll
            for (int i = 0; i < 4; i++)
                #pragma unroll
                for (int j = 0; j < 4; j++)
                    acc[i][j] += av[i] * wr[j];
        }
        __syncthreads();
    }

    float4 bb = *(const float4*)(fc1_b + dq * 4);
    #pragma unroll
    for (int i = 0; i < 4; i++) {
        int pix = pixbase + pxq * 4 + i;
        float4 o;
        o.x = acc[i][0] + bb.x; o.y = acc[i][1] + bb.y;
        o.z = acc[i][2] + bb.z; o.w = acc[i][3] + bb.w;
        *(float4*)(g_xf + ((size_t)b * NPIX + pix) * DLOI + dq * 4) = o;
    }
}

// ---------------- K3: LOI pool --> xv in bf16 hi/lo -------------------------
__global__ __launch_bounds__(128) void k_pool() {
    const int gp = blockIdx.x;
    const int b = gp / NPAIR;
    const int p = gp - b * NPAIR;
    int u, v;
    pair_uv(p, u, v);
    const int d = threadIdx.x;

    const float yu = g_xy[b][u][0], xu = g_xy[b][u][1];
    const float yv = g_xy[b][v][0], xv = g_xy[b][v][1];
    const float* xf = g_xf + (size_t)b * NPIX * DLOI + d;

    __shared__ float stage[1024];
    float gmax = -INFINITY;
    #pragma unroll
    for (int j = 0; j < 32; j++) {
        float lam = (float)j / 31.0f;
        float oml = 1.0f - lam;
        float fy = yu * lam + yv * oml - 0.5f;
        float fx = xu * lam + xv * oml - 0.5f;
        float y0f = fminf(fmaxf(floorf(fy), 0.0f), 127.0f);
        float x0f = fminf(fmaxf(floorf(fx), 0.0f), 127.0f);
        float y1f = fminf(y0f + 1.0f, 127.0f);
        float x1f = fminf(x0f + 1.0f, 127.0f);
        int y0 = (int)y0f, x0 = (int)x0f, y1 = (int)y1f, x1 = (int)x1f;
        float wy0 = fy - y0f, wy1 = y1f - fy;
        float wx0 = fx - x0f, wx1 = x1f - fx;
        float v00 = xf[(y0 * HW + x0) * DLOI];
        float v10 = xf[(y1 * HW + x0) * DLOI];
        float v01 = xf[(y0 * HW + x1) * DLOI];
        float v11 = xf[(y1 * HW + x1) * DLOI];
        float val = v00 * wy1 * wx1 + v10 * wy0 * wx1
                  + v01 * wy1 * wx0 + v11 * wy0 * wx0;
        gmax = fmaxf(gmax, val);
        if ((j & 3) == 3) { stage[d * 8 + (j >> 2)] = gmax; gmax = -INFINITY; }
    }
    __syncthreads();
    __nv_bfloat16* oh = g_xv_hi + (size_t)gp * 1024;
    __nv_bfloat16* ol = g_xv_lo + (size_t)gp * 1024;
    #pragma unroll
    for (int i = 0; i < 8; i++) {
        float s = stage[d + i * 128];
        __nv_bfloat16 h = __float2bfloat16(s);
        oh[d + i * 128] = h;
        ol[d + i * 128] = __float2bfloat16(s - __bfloat162float(h));
    }
}

// ---------------- K4: transpose+split weights (K,N)->(N,K) bf16 hi/lo -------
__global__ __launch_bounds__(256) void k_wsplit(const float* __restrict__ W,
                                                __nv_bfloat16* __restrict__ hi,
                                                __nv_bfloat16* __restrict__ lo) {
    __shared__ float tile[32][33];
    const int tx = threadIdx.x & 31;
    const int ty = threadIdx.x >> 5;     // 0..7
    const int kb = blockIdx.y * 32;
    const int nb = blockIdx.x * 32;
    #pragma unroll
    for (int j = 0; j < 4; j++) {
        int kl = ty * 4 + j;
        tile[kl][tx] = W[(size_t)(kb + kl) * DFC + nb + tx];
    }
    __syncthreads();
    #pragma unroll
    for (int j = 0; j < 4; j++) {
        int nl = ty * 4 + j;
        float v = tile[tx][nl];
        __nv_bfloat16 h = __float2bfloat16(v);
        size_t o = (size_t)(nb + nl) * DFC + kb + tx;
        hi[o] = h;
        lo[o] = __float2bfloat16(v - __bfloat162float(h));
    }
}

// ---------------- K5: mma.sync bf16-split GEMM ------------------------------
// C(16256x1024) = A(16256x1024) * W(1024(n) x 1024(k))^T, hi/lo split (3 terms)
// CTA tile 128x128, BK=32, 8 warps (warp tile 32x64), double-buffered cp.async.
#define SASTRIDE 40   // bf16 elements per smem row (32 + 8 pad)
#define NKCHUNK 96    // 3 splits * (1024/32)

__global__ __launch_bounds__(256) void k_gemm(
        const __nv_bfloat16* __restrict__ Ahi,
        const __nv_bfloat16* __restrict__ Alo,
        const __nv_bfloat16* __restrict__ Bhi,
        const __nv_bfloat16* __restrict__ Blo,
        const float* __restrict__ bias,
        __nv_bfloat16* __restrict__ OutHi,
        __nv_bfloat16* __restrict__ OutLo,
        const float* __restrict__ w3,
        float* __restrict__ part,
        int mode) {
    __shared__ __align__(16) __nv_bfloat16 sA[2][128 * SASTRIDE];
    __shared__ __align__(16) __nv_bfloat16 sB[2][128 * SASTRIDE];
    __shared__ float ps[8][32];

    const int t = threadIdx.x;
    const int wid = t >> 5, lane = t & 31;
    const int wm = wid >> 1, wn = wid & 1;        // warp grid 4x2
    const int bm = blockIdx.y * 128;
    const int bn = blockIdx.x * 128;

    const int ldRow = t >> 2, ldC = (t & 3) * 8;  // per-thread load slot (2 rows)
    float acc[2][8][4];
    #pragma unroll
    for (int i = 0; i < 2; i++)
        #pragma unroll
        for (int j = 0; j < 8; j++)
            #pragma unroll
            for (int q = 0; q < 4; q++) acc[i][j][q] = 0.0f;

    // ldmatrix smem addresses (element offsets precomputed per thread)
    const uint32_t sAu = smem_u32(sA);
    const uint32_t sBu = smem_u32(sB);
    const int aRowSel = wm * 32 + (lane & 15);
    const int aColSel = (lane >> 4) * 8;
    const int bRowSel = wn * 64 + (lane & 7) + ((lane >> 4) << 3);
    const int bColSel = ((lane >> 3) & 1) * 8;

    auto load_stage = [&](int i, int s) {
        const int split = i >> 5;
        const int kc = i & 31;
        const __nv_bfloat16* As = (split == 2) ? Alo : Ahi;
        const __nv_bfloat16* Bs = (split == 1) ? Blo : Bhi;
        #pragma unroll
        for (int u = 0; u < 2; u++) {
            int row = ldRow + u * 64;
            cp16(sAu + (uint32_t)(s * 128 * SASTRIDE + row * SASTRIDE + ldC) * 2,
                 As + (size_t)(bm + row) * DFC + kc * 32 + ldC);
            cp16(sBu + (uint32_t)(s * 128 * SASTRIDE + row * SASTRIDE + ldC) * 2,
                 Bs + (size_t)(bn + row) * DFC + kc * 32 + ldC);
        }
        CP_COMMIT();
    };

    load_stage(0, 0);

    for (int i = 0; i < NKCHUNK; i++) {
        const int cur = i & 1;
        if (i + 1 < NKCHUNK) {
            load_stage(i + 1, cur ^ 1);
            CP_WAIT(1);
        } else {
            CP_WAIT(0);
        }
        __syncthreads();

        const uint32_t aBase = sAu + (uint32_t)(cur * 128 * SASTRIDE) * 2;
        const uint32_t bBase = sBu + (uint32_t)(cur * 128 * SASTRIDE) * 2;
        #pragma unroll
        for (int kk = 0; kk < 32; kk += 16) {
            uint32_t afr[2][4];
            #pragma unroll
            for (int mi = 0; mi < 2; mi++)
                ldm_x4(afr[mi],
                       aBase + (uint32_t)((aRowSel + mi * 16) * SASTRIDE
                                          + kk + aColSel) * 2);
            uint32_t bfr[4][4];
            #pragma unroll
            for (int np = 0; np < 4; np++)
                ldm_x4(bfr[np],
                       bBase + (uint32_t)((bRowSel + np * 16) * SASTRIDE
                                          + kk + bColSel) * 2);
            #pragma unroll
            for (int mi = 0; mi < 2; mi++)
                #pragma unroll
                for (int np = 0; np < 4; np++) {
                    mma16816(acc[mi][np * 2 + 0], afr[mi], &bfr[np][0]);
                    mma16816(acc[mi][np * 2 + 1], afr[mi], &bfr[np][2]);
                }
        }
        __syncthreads();
    }

    // ---------------- epilogue ----------------
    const int q = lane >> 2;          // 0..7 (row in 8-row group)
    const int rr = (lane & 3) * 2;    // col pair base

    if (mode == 0) {
        #pragma unroll
        for (int mi = 0; mi < 2; mi++) {
            #pragma unroll
            for (int ni = 0; ni < 8; ni++) {
                int col = bn + wn * 64 + ni * 8 + rr;
                float b0 = bias[col], b1 = bias[col + 1];
                #pragma unroll
                for (int h = 0; h < 2; h++) {      // h=0: row q, h=1: row q+8
                    int row = bm + wm * 32 + mi * 16 + q + h * 8;
                    float v0 = fmaxf(acc[mi][ni][h * 2 + 0] + b0, 0.0f);
                    float v1 = fmaxf(acc[mi][ni][h * 2 + 1] + b1, 0.0f);
                    __nv_bfloat16 h0 = __float2bfloat16(v0);
                    __nv_bfloat16 h1 = __float2bfloat16(v1);
                    __nv_bfloat162 hp; hp.x = h0; hp.y = h1;
                    __nv_bfloat162 lp;
                    lp.x = __float2bfloat16(v0 - __bfloat162float(h0));
                    lp.y = __float2bfloat16(v1 - __bfloat162float(h1));
                    size_t o = (size_t)row * DFC + col;
                    *(__nv_bfloat162*)(OutHi + o) = hp;
                    *(__nv_bfloat162*)(OutLo + o) = lp;
                }
            }
        }
    } else {
        #pragma unroll
        for (int mi = 0; mi < 2; mi++) {
            float p0 = 0.0f, p1 = 0.0f;          // rows q, q+8
            #pragma unroll
            for (int ni = 0; ni < 8; ni++) {
                int col = bn + wn * 64 + ni * 8 + rr;
                float b0 = bias[col], b1 = bias[col + 1];
                float w0 = w3[col], w1 = w3[col + 1];
                p0 += fmaxf(acc[mi][ni][0] + b0, 0.0f) * w0
                    + fmaxf(acc[mi][ni][1] + b1, 0.0f) * w1;
                p1 += fmaxf(acc[mi][ni][2] + b0, 0.0f) * w0
                    + fmaxf(acc[mi][ni][3] + b1, 0.0f) * w1;
            }
            p0 += __shfl_xor_sync(0xffffffffu, p0, 1);
            p0 += __shfl_xor_sync(0xffffffffu, p0, 2);
            p1 += __shfl_xor_sync(0xffffffffu, p1, 1);
            p1 += __shfl_xor_sync(0xffffffffu, p1, 2);
            if ((lane & 3) == 0) {
                ps[wid][mi * 16 + q] = p0;
                ps[wid][mi * 16 + 8 + q] = p1;
            }
        }
        __syncthreads();
        if (t < 128) {
            int rw = t >> 5, rl = t & 31;
            float tot = ps[rw * 2 + 0][rl] + ps[rw * 2 + 1][rl];
            part[(size_t)(bm + t) * 8 + blockIdx.x] = tot;
        }
    }
}

// ---------------- K6: sum score partials ------------------------------------
__global__ void k_sum(const float* __restrict__ b3, float* __restrict__ out) {
    int i = blockIdx.x * 256 + threadIdx.x;
    if (i >= NROWS) return;
    const float* p = g_part + (size_t)i * 8;
    float s = p[0] + p[1] + p[2] + p[3] + p[4] + p[5] + p[6] + p[7];
    out[i] = s + b3[0];
}

// ---------------- K7: labels (zeros) + lines --------------------------------
__global__ void k_out(float* __restrict__ out) {
    const int gp = blockIdx.x * 256 + threadIdx.x;
    if (gp >= NROWS) return;
    out[NROWS + gp] = 0.0f;
    const int b = gp / NPAIR;
    const int p = gp - b * NPAIR;
    int u, v;
    pair_uv(p, u, v);
    float* L = out + 2 * NROWS + (size_t)gp * 4;
    L[0] = g_xy[b][u][0];
    L[1] = g_xy[b][u][1];
    L[2] = g_xy[b][v][0];
    L[3] = g_xy[b][v][1];
}

// ---------------- launch -----------------------------------------------------
extern "C" void kernel_launch(void* const* d_in, const int* in_sizes, int n_in,
                              void* d_out, int out_size) {
    const float* inputs   = (const float*)d_in[0];
    const float* features = (const float*)d_in[1];
    const float* fc1_w    = (const float*)d_in[2];
    const float* fc1_b    = (const float*)d_in[3];
    const float* w1       = (const float*)d_in[4];
    const float* b1       = (const float*)d_in[5];
    const float* w2       = (const float*)d_in[6];
    const float* b2       = (const float*)d_in[7];
    const float* w3       = (const float*)d_in[8];
    const float* b3       = (const float*)d_in[9];
    float* out = (float*)d_out;

    void *pxvh, *pxvl, *ph1h, *ph1l, *pw1h, *pw1l, *pw2h, *pw2l, *ppart;
    cudaGetSymbolAddress(&pxvh, g_xv_hi);
    cudaGetSymbolAddress(&pxvl, g_xv_lo);
    cudaGetSymbolAddress(&ph1h, g_h1_hi);
    cudaGetSymbolAddress(&ph1l, g_h1_lo);
    cudaGetSymbolAddress(&pw1h, g_w1t_hi);
    cudaGetSymbolAddress(&pw1l, g_w1t_lo);
    cudaGetSymbolAddress(&pw2h, g_w2t_hi);
    cudaGetSymbolAddress(&pw2l, g_w2t_lo);
    cudaGetSymbolAddress(&ppart, g_part);

    const size_t topk_smem = (size_t)(NPIX * 2 + 512) * 4 + 512 * 4 + 64 + 64 + 512;
    cudaFuncSetAttribute(k_topk, cudaFuncAttributeMaxDynamicSharedMemorySize,
                         (int)topk_smem);

    k_topk<<<BATCH, 512, topk_smem>>>(inputs);
    k_xf<<<dim3(NPIX / 32, BATCH), 256>>>(features, fc1_w, fc1_b);
    k_pool<<<NROWS, 128>>>();
    k_wsplit<<<dim3(32, 32), 256>>>(w1, (__nv_bfloat16*)pw1h, (__nv_bfloat16*)pw1l);
    k_wsplit<<<dim3(32, 32), 256>>>(w2, (__nv_bfloat16*)pw2h, (__nv_bfloat16*)pw2l);

    dim3 gg(DFC / 128, NROWS / 128);   // (8, 127)
    k_gemm<<<gg, 256>>>(
        (const __nv_bfloat16*)pxvh, (const __nv_bfloat16*)pxvl,
        (const __nv_bfloat16*)pw1h, (const __nv_bfloat16*)pw1l,
        b1, (__nv_bfloat16*)ph1h, (__nv_bfloat16*)ph1l,
        nullptr, nullptr, 0);
    k_gemm<<<gg, 256>>>(
        (const __nv_bfloat16*)ph1h, (const __nv_bfloat16*)ph1l,
        (const __nv_bfloat16*)pw2h, (const __nv_bfloat16*)pw2l,
        b2, nullptr, nullptr,
        w3, (float*)ppart, 1);

    k_sum<<<(NROWS + 255) / 256, 256>>>(b3, out);
    k_out<<<(NROWS + 255) / 256, 256>>>(out);
}

// round 5
// speedup vs baseline: 1.9950x; 1.1308x over previous
#include <cuda_runtime.h>
#include <cuda_bf16.h>
#include <math.h>
#include <stdint.h>

#define HW 128
#define NPIX 16384
#define BATCH 2
#define KJ 128
#define NPAIR 8128
#define NROWS (BATCH * NPAIR)   // 16256
#define DLOI 128
#define DFC 1024

// ---------------- scratch (device globals; no allocations allowed) ----------
__device__ float g_xf[BATCH * NPIX * DLOI];   // (b, pix, d)
__device__ float g_xy[BATCH][KJ][2];          // (y, x) per junction
__device__ __align__(16) __nv_bfloat16 g_xv_hi[(size_t)NROWS * DFC];
__device__ __align__(16) __nv_bfloat16 g_xv_lo[(size_t)NROWS * DFC];
__device__ __align__(16) __nv_bfloat16 g_h1_hi[(size_t)NROWS * DFC];
__device__ __align__(16) __nv_bfloat16 g_h1_lo[(size_t)NROWS * DFC];
__device__ __align__(16) __nv_bfloat16 g_w1t_hi[DFC * DFC];
__device__ __align__(16) __nv_bfloat16 g_w1t_lo[DFC * DFC];
__device__ __align__(16) __nv_bfloat16 g_w2t_hi[DFC * DFC];
__device__ __align__(16) __nv_bfloat16 g_w2t_lo[DFC * DFC];
__device__ float g_part[(size_t)NROWS * 8];

// ---------------- helpers ----------------------------------------------------
__device__ __forceinline__ uint32_t smem_u32(const void* p) {
    uint32_t a;
    asm("{ .reg .u64 t; cvta.to.shared.u64 t, %1; cvt.u32.u64 %0, t; }"
        : "=r"(a) : "l"(p));
    return a;
}
__device__ __forceinline__ void cp16(uint32_t s, const void* g) {
    asm volatile("cp.async.cg.shared.global [%0], [%1], 16;"
                 :: "r"(s), "l"(g) : "memory");
}
#define CP_COMMIT() asm volatile("cp.async.commit_group;" ::: "memory")
#define CP_WAIT(n)  asm volatile("cp.async.wait_group %0;" :: "n"(n) : "memory")

__device__ __forceinline__ void ldm_x4(uint32_t* r, uint32_t addr) {
    asm volatile("ldmatrix.sync.aligned.m8n8.x4.shared.b16 {%0,%1,%2,%3}, [%4];"
                 : "=r"(r[0]), "=r"(r[1]), "=r"(r[2]), "=r"(r[3]) : "r"(addr));
}
__device__ __forceinline__ void mma16816(float* c, const uint32_t* a,
                                         const uint32_t* b) {
    asm volatile(
        "mma.sync.aligned.m16n8k16.row.col.f32.bf16.bf16.f32 "
        "{%0,%1,%2,%3}, {%4,%5,%6,%7}, {%8,%9}, {%0,%1,%2,%3};"
        : "+f"(c[0]), "+f"(c[1]), "+f"(c[2]), "+f"(c[3])
        : "r"(a[0]), "r"(a[1]), "r"(a[2]), "r"(a[3]), "r"(b[0]), "r"(b[1]));
}

// ---------------- pair index helpers (triu_indices(K=128, k=1)) -------------
__device__ __forceinline__ int pair_off(int u) { return u * (255 - u) / 2; }
__device__ __forceinline__ void pair_uv(int p, int& u, int& v) {
    int uu = (int)((255.0 - sqrt(255.0 * 255.0 - 8.0 * (double)p)) * 0.5);
    if (uu < 0) uu = 0;
    if (uu > 126) uu = 126;
    while (uu < 126 && pair_off(uu + 1) <= p) uu++;
    while (uu > 0 && pair_off(uu) > p) uu--;
    u = uu;
    v = uu + 1 + (p - pair_off(uu));
}

// ---------------- K1: jmap + NMS + exact top-128 + junction coords ----------
__global__ void k_topk(const float* __restrict__ inputs) {
    extern __shared__ float sh[];
    float* smap = sh;
    float* nmsv = smap + NPIX;
    float* bv   = nmsv + NPIX;
    int*   bi   = (int*)(bv + 512);
    float* wv   = (float*)(bi + 512);
    int*   wi   = (int*)(wv + 16);
    int*   topidx = wi + 16;

    const int b = blockIdx.x;
    const int t = threadIdx.x;
    const float* in0 = inputs + (size_t)b * 5 * NPIX;
    const float* in1 = in0 + NPIX;

    for (int i = t; i < NPIX; i += 512) {
        float x0 = in0[i], x1 = in1[i];
        float m = fmaxf(x0, x1);
        float e0 = expf(x0 - m), e1 = expf(x1 - m);
        smap[i] = e1 / (e0 + e1);
    }
    __syncthreads();

    float bval = -1.0f;
    int bidx = t * 32;
    for (int j = 0; j < 32; j++) {
        int idx = t * 32 + j;
        int y = idx >> 7, x = idx & 127;
        float v = smap[idx];
        float m = v;
        #pragma unroll
        for (int dy = -1; dy <= 1; dy++) {
            int yy = y + dy;
            if (yy < 0 || yy >= HW) continue;
            #pragma unroll
            for (int dx = -1; dx <= 1; dx++) {
                int xx = x + dx;
                if (xx < 0 || xx >= HW) continue;
                m = fmaxf(m, smap[yy * HW + xx]);
            }
        }
        float nv = (v == m) ? v : 0.0f;
        nmsv[idx] = nv;
        if (nv > bval) { bval = nv; bidx = idx; }
    }
    bv[t] = bval; bi[t] = bidx;
    __syncthreads();

    for (int r = 0; r < KJ; r++) {
        float v = bv[t];
        int ix = bi[t];
        #pragma unroll
        for (int off = 16; off; off >>= 1) {
            float v2 = __shfl_down_sync(0xffffffffu, v, off);
            int   i2 = __shfl_down_sync(0xffffffffu, ix, off);
            if (v2 > v || (v2 == v && i2 < ix)) { v = v2; ix = i2; }
        }
        if ((t & 31) == 0) { wv[t >> 5] = v; wi[t >> 5] = ix; }
        __syncthreads();
        if (t < 32) {
            float v3 = (t < 16) ? wv[t] : -2.0f;
            int   i3 = (t < 16) ? wi[t] : 0x7fffffff;
            #pragma unroll
            for (int off = 8; off; off >>= 1) {
                float v2 = __shfl_down_sync(0xffffffffu, v3, off);
                int   i2 = __shfl_down_sync(0xffffffffu, i3, off);
                if (v2 > v3 || (v2 == v3 && i2 < i3)) { v3 = v2; i3 = i2; }
            }
            if (t == 0) topidx[r] = i3;
        }
        __syncthreads();
        int win = topidx[r];
        if (t == (win >> 5)) {
            nmsv[win] = -1.0f;
            float nb = -1.0f;
            int nbi = t * 32;
            for (int j = 0; j < 32; j++) {
                float nv = nmsv[t * 32 + j];
                if (nv > nb) { nb = nv; nbi = t * 32 + j; }
            }
            bv[t] = nb; bi[t] = nbi;
        }
        __syncthreads();
    }

    if (t < KJ) {
        int idx = topidx[t];
        const float* in3 = in0 + 3 * NPIX;
        const float* in4 = in0 + 4 * NPIX;
        float sy = 1.0f / (1.0f + expf(-in3[idx]));
        float sx = 1.0f / (1.0f + expf(-in4[idx]));
        g_xy[b][t][0] = (float)(idx >> 7) + sy;
        g_xy[b][t][1] = (float)(idx & 127) + sx;
    }
}

// ---------------- K2: xf[b,pix,d] = sum_c features[b,c,pix]*fc1_w[d,c]+b ----
__global__ __launch_bounds__(256) void k_xf(const float* __restrict__ features,
                                            const float* __restrict__ fc1_w,
                                            const float* __restrict__ fc1_b) {
    __shared__ float As[32][40];
    __shared__ float Ws[32][128];
    const int b = blockIdx.y;
    const int pixbase = blockIdx.x * 32;
    const int t = threadIdx.x;
    const int pxq = t & 7;
    const int dq  = t >> 3;
    float acc[4][4] = {};

    const float* F = features + (size_t)b * 256 * NPIX + pixbase;

    for (int c0 = 0; c0 < 256; c0 += 32) {
        {
            int c = t >> 3, px4 = (t & 7) * 4;
            float4 a4 = *(const float4*)(F + (size_t)(c0 + c) * NPIX + px4);
            As[c][px4 + 0] = a4.x; As[c][px4 + 1] = a4.y;
            As[c][px4 + 2] = a4.z; As[c][px4 + 3] = a4.w;
        }
        #pragma unroll
        for (int kk = 0; kk < 4; kk++) {
            int e = t + kk * 256;
            int d = e >> 3, c4 = (e & 7) * 4;
            float4 w4 = *(const float4*)(fc1_w + d * 256 + c0 + c4);
            Ws[c4 + 0][d] = w4.x; Ws[c4 + 1][d] = w4.y;
            Ws[c4 + 2][d] = w4.z; Ws[c4 + 3][d] = w4.w;
        }
        __syncthreads();
        #pragma unroll
        for (int c = 0; c < 32; c++) {
            float4 a4 = *(const float4*)&As[c][pxq * 4];
            float4 w4 = *(const float4*)&Ws[c][dq * 4];
            float av[4] = {a4.x, a4.y, a4.z, a4.w};
            float wr[4] = {w4.x, w4.y, w4.z, w4.w};
            #pragma unroll
            for (int i = 0; i < 4; i++)
                #pragma unroll
                for (int j = 0; j < 4; j++)
                    acc[i][j] += av[i] * wr[j];
        }
        __syncthreads();
    }

    float4 bb = *(const float4*)(fc1_b + dq * 4);
    #pragma unroll
    for (int i = 0; i < 4; i++) {
        int pix = pixbase + pxq * 4 + i;
        float4 o;
        o.x = acc[i][0] + bb.x; o.y = acc[i][1] + bb.y;
        o.z = acc[i][2] + bb.z; o.w = acc[i][3] + bb.w;
        *(float4*)(g_xf + ((size_t)b * NPIX + pix) * DLOI + dq * 4) = o;
    }
}

// ---------------- K3: LOI pool --> xv in bf16 hi/lo -------------------------
__global__ __launch_bounds__(128) void k_pool() {
    const int gp = blockIdx.x;
    const int b = gp / NPAIR;
    const int p = gp - b * NPAIR;
    int u, v;
    pair_uv(p, u, v);
    const int d = threadIdx.x;

    const float yu = g_xy[b][u][0], xu = g_xy[b][u][1];
    const float yv = g_xy[b][v][0], xv = g_xy[b][v][1];
    const float* xf = g_xf + (size_t)b * NPIX * DLOI + d;

    __shared__ float stage[1024];
    float gmax = -INFINITY;
    #pragma unroll
    for (int j = 0; j < 32; j++) {
        float lam = (float)j / 31.0f;
        float oml = 1.0f - lam;
        float fy = yu * lam + yv * oml - 0.5f;
        float fx = xu * lam + xv * oml - 0.5f;
        float y0f = fminf(fmaxf(floorf(fy), 0.0f), 127.0f);
        float x0f = fminf(fmaxf(floorf(fx), 0.0f), 127.0f);
        float y1f = fminf(y0f + 1.0f, 127.0f);
        float x1f = fminf(x0f + 1.0f, 127.0f);
        int y0 = (int)y0f, x0 = (int)x0f, y1 = (int)y1f, x1 = (int)x1f;
        float wy0 = fy - y0f, wy1 = y1f - fy;
        float wx0 = fx - x0f, wx1 = x1f - fx;
        float v00 = xf[(y0 * HW + x0) * DLOI];
        float v10 = xf[(y1 * HW + x0) * DLOI];
        float v01 = xf[(y0 * HW + x1) * DLOI];
        float v11 = xf[(y1 * HW + x1) * DLOI];
        float val = v00 * wy1 * wx1 + v10 * wy0 * wx1
                  + v01 * wy1 * wx0 + v11 * wy0 * wx0;
        gmax = fmaxf(gmax, val);
        if ((j & 3) == 3) { stage[d * 8 + (j >> 2)] = gmax; gmax = -INFINITY; }
    }
    __syncthreads();
    __nv_bfloat16* oh = g_xv_hi + (size_t)gp * 1024;
    __nv_bfloat16* ol = g_xv_lo + (size_t)gp * 1024;
    #pragma unroll
    for (int i = 0; i < 8; i++) {
        float s = stage[d + i * 128];
        __nv_bfloat16 h = __float2bfloat16(s);
        oh[d + i * 128] = h;
        ol[d + i * 128] = __float2bfloat16(s - __bfloat162float(h));
    }
}

// ---------------- K4: transpose+split weights (K,N)->(N,K) bf16 hi/lo -------
__global__ __launch_bounds__(256) void k_wsplit(const float* __restrict__ W,
                                                __nv_bfloat16* __restrict__ hi,
                                                __nv_bfloat16* __restrict__ lo) {
    __shared__ float tile[32][33];
    const int tx = threadIdx.x & 31;
    const int ty = threadIdx.x >> 5;     // 0..7
    const int kb = blockIdx.y * 32;
    const int nb = blockIdx.x * 32;
    #pragma unroll
    for (int j = 0; j < 4; j++) {
        int kl = ty * 4 + j;
        tile[kl][tx] = W[(size_t)(kb + kl) * DFC + nb + tx];
    }
    __syncthreads();
    #pragma unroll
    for (int j = 0; j < 4; j++) {
        int nl = ty * 4 + j;
        float v = tile[tx][nl];
        __nv_bfloat16 h = __float2bfloat16(v);
        size_t o = (size_t)(nb + nl) * DFC + kb + tx;
        hi[o] = h;
        lo[o] = __float2bfloat16(v - __bfloat162float(h));
    }
}

// ---------------- K5: mma.sync bf16-split GEMM, 4-stage pipeline ------------
// C(16256x1024) = A(16256x1024) * W(1024(n) x 1024(k))^T, hi/lo split (3 terms)
// CTA tile 128x128, BK=32, 8 warps (warp tile 32x64).
#define SASTRIDE 40   // bf16 elements per smem row (32 + 8 pad)
#define NKCHUNK 96    // 3 splits * (1024/32)
#define NSTG 4
#define STG_ELEMS (128 * SASTRIDE)              // per operand per stage
#define GEMM_DSMEM (NSTG * STG_ELEMS * 2 * 2)   // 81920 bytes

__global__ __launch_bounds__(256, 2) void k_gemm(
        const __nv_bfloat16* __restrict__ Ahi,
        const __nv_bfloat16* __restrict__ Alo,
        const __nv_bfloat16* __restrict__ Bhi,
        const __nv_bfloat16* __restrict__ Blo,
        const float* __restrict__ bias,
        __nv_bfloat16* __restrict__ OutHi,
        __nv_bfloat16* __restrict__ OutLo,
        const float* __restrict__ w3,
        float* __restrict__ part,
        int mode) {
    extern __shared__ __align__(16) __nv_bfloat16 dsm[];
    __nv_bfloat16* sAbase = dsm;                       // NSTG stages
    __nv_bfloat16* sBbase = dsm + NSTG * STG_ELEMS;    // NSTG stages

    const int t = threadIdx.x;
    const int wid = t >> 5, lane = t & 31;
    const int wm = wid >> 1, wn = wid & 1;        // warp grid 4x2
    const int bm = blockIdx.y * 128;
    const int bn = blockIdx.x * 128;

    const int ldRow = t >> 2, ldC = (t & 3) * 8;  // per-thread load slot (2 rows)
    float acc[2][8][4];
    #pragma unroll
    for (int i = 0; i < 2; i++)
        #pragma unroll
        for (int j = 0; j < 8; j++)
            #pragma unroll
            for (int q = 0; q < 4; q++) acc[i][j][q] = 0.0f;

    const uint32_t sAu = smem_u32(sAbase);
    const uint32_t sBu = smem_u32(sBbase);
    const int aRowSel = wm * 32 + (lane & 15);
    const int aColSel = (lane >> 4) * 8;
    const int bRowSel = wn * 64 + (lane & 7) + ((lane >> 4) << 3);
    const int bColSel = ((lane >> 3) & 1) * 8;

    auto load_stage = [&](int i, int s) {
        const int split = i >> 5;
        const int kc = i & 31;
        const __nv_bfloat16* As = (split == 2) ? Alo : Ahi;
        const __nv_bfloat16* Bs = (split == 1) ? Blo : Bhi;
        #pragma unroll
        for (int u = 0; u < 2; u++) {
            int row = ldRow + u * 64;
            cp16(sAu + (uint32_t)(s * STG_ELEMS + row * SASTRIDE + ldC) * 2,
                 As + (size_t)(bm + row) * DFC + kc * 32 + ldC);
            cp16(sBu + (uint32_t)(s * STG_ELEMS + row * SASTRIDE + ldC) * 2,
                 Bs + (size_t)(bn + row) * DFC + kc * 32 + ldC);
        }
    };

    // prefetch 3 stages
    #pragma unroll
    for (int p = 0; p < NSTG - 1; p++) {
        load_stage(p, p);
        CP_COMMIT();
    }

    for (int i = 0; i < NKCHUNK; i++) {
        const int cur = i & (NSTG - 1);
        CP_WAIT(NSTG - 2);      // stage `cur` complete
        __syncthreads();        // all warps done with stage being overwritten

        const uint32_t aBase = sAu + (uint32_t)(cur * STG_ELEMS) * 2;
        const uint32_t bBase = sBu + (uint32_t)(cur * STG_ELEMS) * 2;
        #pragma unroll
        for (int kk = 0; kk < 32; kk += 16) {
            uint32_t afr[2][4];
            #pragma unroll
            for (int mi = 0; mi < 2; mi++)
                ldm_x4(afr[mi],
                       aBase + (uint32_t)((aRowSel + mi * 16) * SASTRIDE
                                          + kk + aColSel) * 2);
            uint32_t bfr[4][4];
            #pragma unroll
            for (int np = 0; np < 4; np++)
                ldm_x4(bfr[np],
                       bBase + (uint32_t)((bRowSel + np * 16) * SASTRIDE
                                          + kk + bColSel) * 2);
            #pragma unroll
            for (int mi = 0; mi < 2; mi++)
                #pragma unroll
                for (int np = 0; np < 4; np++) {
                    mma16816(acc[mi][np * 2 + 0], afr[mi], &bfr[np][0]);
                    mma16816(acc[mi][np * 2 + 1], afr[mi], &bfr[np][2]);
                }
        }
        if (i + NSTG - 1 < NKCHUNK)
            load_stage(i + NSTG - 1, (i + NSTG - 1) & (NSTG - 1));
        CP_COMMIT();            // commit (possibly empty) to keep group count
    }

    // ---------------- epilogue ----------------
    const int q = lane >> 2;          // 0..7 (row in 8-row group)
    const int rr = (lane & 3) * 2;    // col pair base

    if (mode == 0) {
        #pragma unroll
        for (int mi = 0; mi < 2; mi++) {
            #pragma unroll
            for (int ni = 0; ni < 8; ni++) {
                int col = bn + wn * 64 + ni * 8 + rr;
                float b0 = bias[col], b1 = bias[col + 1];
                #pragma unroll
                for (int h = 0; h < 2; h++) {      // h=0: row q, h=1: row q+8
                    int row = bm + wm * 32 + mi * 16 + q + h * 8;
                    float v0 = fmaxf(acc[mi][ni][h * 2 + 0] + b0, 0.0f);
                    float v1 = fmaxf(acc[mi][ni][h * 2 + 1] + b1, 0.0f);
                    __nv_bfloat16 h0 = __float2bfloat16(v0);
                    __nv_bfloat16 h1 = __float2bfloat16(v1);
                    __nv_bfloat162 hp; hp.x = h0; hp.y = h1;
                    __nv_bfloat162 lp;
                    lp.x = __float2bfloat16(v0 - __bfloat162float(h0));
                    lp.y = __float2bfloat16(v1 - __bfloat162float(h1));
                    size_t o = (size_t)row * DFC + col;
                    *(__nv_bfloat162*)(OutHi + o) = hp;
                    *(__nv_bfloat162*)(OutLo + o) = lp;
                }
            }
        }
    } else {
        __syncthreads();                       // before reusing smem as ps
        float* ps = (float*)dsm;               // [8][32]
        #pragma unroll
        for (int mi = 0; mi < 2; mi++) {
            float p0 = 0.0f, p1 = 0.0f;        // rows q, q+8
            #pragma unroll
            for (int ni = 0; ni < 8; ni++) {
                int col = bn + wn * 64 + ni * 8 + rr;
                float b0 = bias[col], b1 = bias[col + 1];
                float w0 = w3[col], w1 = w3[col + 1];
                p0 += fmaxf(acc[mi][ni][0] + b0, 0.0f) * w0
                    + fmaxf(acc[mi][ni][1] + b1, 0.0f) * w1;
                p1 += fmaxf(acc[mi][ni][2] + b0, 0.0f) * w0
                    + fmaxf(acc[mi][ni][3] + b1, 0.0f) * w1;
            }
            p0 += __shfl_xor_sync(0xffffffffu, p0, 1);
            p0 += __shfl_xor_sync(0xffffffffu, p0, 2);
            p1 += __shfl_xor_sync(0xffffffffu, p1, 1);
            p1 += __shfl_xor_sync(0xffffffffu, p1, 2);
            if ((lane & 3) == 0) {
                ps[wid * 32 + mi * 16 + q] = p0;
                ps[wid * 32 + mi * 16 + 8 + q] = p1;
            }
        }
        __syncthreads();
        if (t < 128) {
            int rw = t >> 5, rl = t & 31;
            float tot = ps[(rw * 2 + 0) * 32 + rl] + ps[(rw * 2 + 1) * 32 + rl];
            part[(size_t)(bm + t) * 8 + blockIdx.x] = tot;
        }
    }
}

// ---------------- K6: scores + labels + lines (fused) -----------------------
__global__ void k_out(const float* __restrict__ b3, float* __restrict__ out) {
    const int gp = blockIdx.x * 256 + threadIdx.x;
    if (gp >= NROWS) return;
    const float* pp = g_part + (size_t)gp * 8;
    float s = pp[0] + pp[1] + pp[2] + pp[3] + pp[4] + pp[5] + pp[6] + pp[7];
    out[gp] = s + b3[0];
    out[NROWS + gp] = 0.0f;
    const int b = gp / NPAIR;
    const int p = gp - b * NPAIR;
    int u, v;
    pair_uv(p, u, v);
    float* L = out + 2 * NROWS + (size_t)gp * 4;
    L[0] = g_xy[b][u][0];
    L[1] = g_xy[b][u][1];
    L[2] = g_xy[b][v][0];
    L[3] = g_xy[b][v][1];
}

// ---------------- launch -----------------------------------------------------
extern "C" void kernel_launch(void* const* d_in, const int* in_sizes, int n_in,
                              void* d_out, int out_size) {
    const float* inputs   = (const float*)d_in[0];
    const float* features = (const float*)d_in[1];
    const float* fc1_w    = (const float*)d_in[2];
    const float* fc1_b    = (const float*)d_in[3];
    const float* w1       = (const float*)d_in[4];
    const float* b1       = (const float*)d_in[5];
    const float* w2       = (const float*)d_in[6];
    const float* b2       = (const float*)d_in[7];
    const float* w3       = (const float*)d_in[8];
    const float* b3       = (const float*)d_in[9];
    float* out = (float*)d_out;

    void *pxvh, *pxvl, *ph1h, *ph1l, *pw1h, *pw1l, *pw2h, *pw2l, *ppart;
    cudaGetSymbolAddress(&pxvh, g_xv_hi);
    cudaGetSymbolAddress(&pxvl, g_xv_lo);
    cudaGetSymbolAddress(&ph1h, g_h1_hi);
    cudaGetSymbolAddress(&ph1l, g_h1_lo);
    cudaGetSymbolAddress(&pw1h, g_w1t_hi);
    cudaGetSymbolAddress(&pw1l, g_w1t_lo);
    cudaGetSymbolAddress(&pw2h, g_w2t_hi);
    cudaGetSymbolAddress(&pw2l, g_w2t_lo);
    cudaGetSymbolAddress(&ppart, g_part);

    const size_t topk_smem = (size_t)(NPIX * 2 + 512) * 4 + 512 * 4 + 64 + 64 + 512;
    cudaFuncSetAttribute(k_topk, cudaFuncAttributeMaxDynamicSharedMemorySize,
                         (int)topk_smem);
    cudaFuncSetAttribute(k_gemm, cudaFuncAttributeMaxDynamicSharedMemorySize,
                         GEMM_DSMEM);

    k_topk<<<BATCH, 512, topk_smem>>>(inputs);
    k_xf<<<dim3(NPIX / 32, BATCH), 256>>>(features, fc1_w, fc1_b);
    k_pool<<<NROWS, 128>>>();
    k_wsplit<<<dim3(32, 32), 256>>>(w1, (__nv_bfloat16*)pw1h, (__nv_bfloat16*)pw1l);
    k_wsplit<<<dim3(32, 32), 256>>>(w2, (__nv_bfloat16*)pw2h, (__nv_bfloat16*)pw2l);

    dim3 gg(DFC / 128, NROWS / 128);   // (8, 127)
    k_gemm<<<gg, 256, GEMM_DSMEM>>>(
        (const __nv_bfloat16*)pxvh, (const __nv_bfloat16*)pxvl,
        (const __nv_bfloat16*)pw1h, (const __nv_bfloat16*)pw1l,
        b1, (__nv_bfloat16*)ph1h, (__nv_bfloat16*)ph1l,
        nullptr, nullptr, 0);
    k_gemm<<<gg, 256, GEMM_DSMEM>>>(
        (const __nv_bfloat16*)ph1h, (const __nv_bfloat16*)ph1l,
        (const __nv_bfloat16*)pw2h, (const __nv_bfloat16*)pw2l,
        b2, nullptr, nullptr,
        w3, (float*)ppart, 1);

    k_out<<<(NROWS + 255) / 256, 256>>>(b3, out);
}